// round 8
// baseline (speedup 1.0000x reference)
#include <cuda_runtime.h>
#include <cuda_fp16.h>

// Morphological dilation2d, K=7, PAD=3 (zero padding = nn.Unfold), then ReLU.
// out[b,c,h,w] = max(0, max_{i,j}( xp[b,c,h+i,w+j] + weight[c,i,j] ))
// Packed fp16x2 (HADD2 + HMNMX2); ReLU folded into acc init (=0).
// Software-pipelined: next row's data + next kernel-row's weights prefetched
// into registers while computing the current row.
//
// x:      (16, 96, 128, 128) fp32 -> d_in[0]
// weight: (96, 7, 7)         fp32 -> d_in[1]
// out:    fp32

#define HH    128
#define WW    128
#define CC    96
#define BB    16
#define RPC   32            // output rows per CTA
#define SR    38            // smem rows = RPC + 6
#define SROWH 136           // smem row stride in HALVES (272B)
#define NT    256

__device__ __forceinline__ __half2 u2h(unsigned u) { return *reinterpret_cast<__half2*>(&u); }

__global__ __launch_bounds__(NT, 4)
void morph7x7_h2_kernel(const float* __restrict__ x,
                        const float* __restrict__ wt,
                        float* __restrict__ out) {
    __shared__ __half xs[SR * SROWH];
    __shared__ unsigned wsm2[49];           // half2 broadcast (w,w) per tap

    const int bid   = blockIdx.x;
    const int rtile = bid & 3;
    const int plane = bid >> 2;             // b*CC + c
    const int c     = plane % CC;
    const int R0    = rtile * RPC;

    const float* gx = x   + (size_t)plane * (HH * WW);
    float*       go = out + (size_t)plane * (HH * WW);
    const int tid = threadIdx.x;

    // ---- zero slab (borders must be literal zeros) ----
    const uint4 z4 = {0u, 0u, 0u, 0u};
    #pragma unroll
    for (int i = tid; i < (SR * SROWH) / 8; i += NT)
        reinterpret_cast<uint4*>(xs)[i] = z4;
    if (tid < 49) {
        __half hw = __float2half_rn(wt[c * 49 + tid]);
        __half2 w2 = __half2half2(hw);
        wsm2[tid] = *reinterpret_cast<unsigned*>(&w2);
    }
    __syncthreads();

    // ---- load interior rows [g0,g1), fp32 -> fp16, data at half-col 4 ----
    const int g0 = (R0 - 3 > 0) ? R0 - 3 : 0;
    const int g1 = (R0 + 35 < HH) ? R0 + 35 : HH;
    const int n4 = (g1 - g0) * 32;          // float4 count
    #pragma unroll
    for (int idx = tid; idx < n4; idx += NT) {
        const int rr = idx >> 5;
        const int c4 = idx & 31;
        const int g  = g0 + rr;
        float4 v = reinterpret_cast<const float4*>(gx + g * WW)[c4];
        __half2 p0 = __floats2half2_rn(v.x, v.y);
        __half2 p1 = __floats2half2_rn(v.z, v.w);
        __half2* dst = reinterpret_cast<__half2*>(&xs[(g + 3 - R0) * SROWH + 4 + c4 * 4]);
        dst[0] = p0;
        dst[1] = p1;
    }
    __syncthreads();

    // ---- compute: thread = 8 cols x 2 rows, software-pipelined over 8 rows ----
    const int tx    = tid & 15;
    const int ty    = tid >> 4;
    const int cbase = tx * 8;               // output col base; LDS.128-aligned reads
    const int r0    = ty * 2;

    // S[0..3]=0 pad; taps for output col w are S[w+1 .. w+7].
    const uint4* rbase = reinterpret_cast<const uint4*>(&xs[r0 * SROWH + cbase]);
    const int rstride4 = SROWH / 8;         // uint4 per smem row = 17

    __half2 acc0[4], acc1[4];
    const __half2 h2z = __float2half2_rn(0.0f);
    #pragma unroll
    for (int p = 0; p < 4; ++p) { acc0[p] = h2z; acc1[p] = h2z; }   // folds ReLU

    // prime pipeline: row 0 data + weight row 0
    uint4 A = rbase[0];
    uint4 B = rbase[1];
    unsigned wcur[7], wprev[7];
    #pragma unroll
    for (int j = 0; j < 7; ++j) { wcur[j] = wsm2[j]; wprev[j] = 0u; }

    #pragma unroll
    for (int s = 0; s < 8; ++s) {
        unsigned h[8] = {A.x, A.y, A.z, A.w, B.x, B.y, B.z, B.w};

        // ---- prefetch next row + next weight row BEFORE compute ----
        if (s < 7) {
            A = rbase[(s + 1) * rstride4];
            B = rbase[(s + 1) * rstride4 + 1];
        }
        unsigned wnext[7];
        if (s < 6) {
            #pragma unroll
            for (int j = 0; j < 7; ++j) wnext[j] = wsm2[(s + 1) * 7 + j];
        }

        unsigned sft[7];
        #pragma unroll
        for (int m = 0; m < 7; ++m) sft[m] = __byte_perm(h[m], h[m + 1], 0x5432);

        // tap j, output pair p: taps = j even -> sft[j/2+p], j odd -> h[(j+1)/2+p]
        // acc0 uses weight row s (s<7); acc1 uses weight row s-1 (s>0). Interleaved.
        #pragma unroll
        for (int j = 0; j < 7; ++j) {
            const __half2 w0 = u2h(wcur[j]);
            const __half2 w1 = u2h(wprev[j]);
            #pragma unroll
            for (int p = 0; p < 4; ++p) {
                const __half2 tap = (j & 1) ? u2h(h[((j + 1) >> 1) + p])
                                            : u2h(sft[(j >> 1) + p]);
                if (s < 7) acc0[p] = __hmax2(acc0[p], __hadd2(tap, w0));
                if (s > 0) acc1[p] = __hmax2(acc1[p], __hadd2(tap, w1));
            }
        }

        // rotate weight rows (register renaming under full unroll)
        #pragma unroll
        for (int j = 0; j < 7; ++j) wprev[j] = wcur[j];
        if (s < 6) {
            #pragma unroll
            for (int j = 0; j < 7; ++j) wcur[j] = wnext[j];
        }
    }

    // ---- convert fp16 -> fp32, store 2x STG.128 per row ----
    {
        float2 f0 = __half22float2(acc0[0]);
        float2 f1 = __half22float2(acc0[1]);
        float2 f2 = __half22float2(acc0[2]);
        float2 f3 = __half22float2(acc0[3]);
        float4* op = reinterpret_cast<float4*>(&go[(R0 + r0) * WW + cbase]);
        op[0] = make_float4(f0.x, f0.y, f1.x, f1.y);
        op[1] = make_float4(f2.x, f2.y, f3.x, f3.y);
    }
    {
        float2 f0 = __half22float2(acc1[0]);
        float2 f1 = __half22float2(acc1[1]);
        float2 f2 = __half22float2(acc1[2]);
        float2 f3 = __half22float2(acc1[3]);
        float4* op = reinterpret_cast<float4*>(&go[(R0 + r0 + 1) * WW + cbase]);
        op[0] = make_float4(f0.x, f0.y, f1.x, f1.y);
        op[1] = make_float4(f2.x, f2.y, f3.x, f3.y);
    }
}

extern "C" void kernel_launch(void* const* d_in, const int* in_sizes, int n_in,
                              void* d_out, int out_size) {
    const float* x  = (const float*)d_in[0];
    const float* wt = (const float*)d_in[1];
    float* out = (float*)d_out;
    morph7x7_h2_kernel<<<BB * CC * 4, NT>>>(x, wt, out);
}

// round 9
// speedup vs baseline: 1.2246x; 1.2246x over previous
#include <cuda_runtime.h>
#include <cuda_fp16.h>

// Morphological dilation2d, K=7, PAD=3 (zero padding = nn.Unfold), then ReLU.
// out[b,c,h,w] = max(0, max_{i,j}( xp[b,c,h+i,w+j] + weight[c,i,j] ))
// Packed fp16x2 (HADD2 + HMNMX2); ReLU folded into acc init (=0).
// Occupancy-optimized: weights read inline from smem (broadcast LDS), no
// register prefetch arrays -> fits 6 CTAs/SM (48 warps, 75% occ).
//
// x:      (16, 96, 128, 128) fp32 -> d_in[0]
// weight: (96, 7, 7)         fp32 -> d_in[1]
// out:    fp32

#define HH    128
#define WW    128
#define CC    96
#define BB    16
#define RPC   32            // output rows per CTA
#define SR    38            // smem rows = RPC + 6
#define SROWH 136           // smem row stride in HALVES (272B)
#define NT    256

__device__ __forceinline__ __half2 u2h(unsigned u) { return *reinterpret_cast<__half2*>(&u); }

__global__ __launch_bounds__(NT, 6)
void morph7x7_h2_kernel(const float* __restrict__ x,
                        const float* __restrict__ wt,
                        float* __restrict__ out) {
    __shared__ __half xs[SR * SROWH];
    __shared__ unsigned wsm2[49];           // half2 broadcast (w,w) per tap

    const int bid   = blockIdx.x;
    const int rtile = bid & 3;
    const int plane = bid >> 2;             // b*CC + c
    const int c     = plane % CC;
    const int R0    = rtile * RPC;

    const float* gx = x   + (size_t)plane * (HH * WW);
    float*       go = out + (size_t)plane * (HH * WW);
    const int tid = threadIdx.x;

    // ---- zero slab (borders must be literal zeros) ----
    const uint4 z4 = {0u, 0u, 0u, 0u};
    #pragma unroll
    for (int i = tid; i < (SR * SROWH) / 8; i += NT)
        reinterpret_cast<uint4*>(xs)[i] = z4;
    if (tid < 49) {
        __half hw = __float2half_rn(wt[c * 49 + tid]);
        __half2 w2 = __half2half2(hw);
        wsm2[tid] = *reinterpret_cast<unsigned*>(&w2);
    }
    __syncthreads();

    // ---- load interior rows [g0,g1), fp32 -> fp16, data at half-col 4 ----
    const int g0 = (R0 - 3 > 0) ? R0 - 3 : 0;
    const int g1 = (R0 + 35 < HH) ? R0 + 35 : HH;
    const int n4 = (g1 - g0) * 32;          // float4 count
    #pragma unroll
    for (int idx = tid; idx < n4; idx += NT) {
        const int rr = idx >> 5;
        const int c4 = idx & 31;
        const int g  = g0 + rr;
        float4 v = reinterpret_cast<const float4*>(gx + g * WW)[c4];
        __half2 p0 = __floats2half2_rn(v.x, v.y);
        __half2 p1 = __floats2half2_rn(v.z, v.w);
        __half2* dst = reinterpret_cast<__half2*>(&xs[(g + 3 - R0) * SROWH + 4 + c4 * 4]);
        dst[0] = p0;
        dst[1] = p1;
    }
    __syncthreads();

    // ---- compute: thread = 8 cols x 2 rows ----
    const int tx    = tid & 15;
    const int ty    = tid >> 4;
    const int cbase = tx * 8;               // output col base; LDS.128-aligned reads
    const int r0    = ty * 2;

    // S[0..3]=0 pad; taps for output col w are S[w+1 .. w+7].
    const uint4* rbase = reinterpret_cast<const uint4*>(&xs[r0 * SROWH + cbase]);
    const int rstride4 = SROWH / 8;         // uint4 per smem row = 17

    __half2 acc0[4], acc1[4];
    const __half2 h2z = __float2half2_rn(0.0f);
    #pragma unroll
    for (int p = 0; p < 4; ++p) { acc0[p] = h2z; acc1[p] = h2z; }   // folds ReLU

    #pragma unroll
    for (int s = 0; s < 8; ++s) {
        const uint4 A = rbase[s * rstride4];
        const uint4 B = rbase[s * rstride4 + 1];
        unsigned h[8] = {A.x, A.y, A.z, A.w, B.x, B.y, B.z, B.w};
        unsigned sft[7];
        #pragma unroll
        for (int m = 0; m < 7; ++m) sft[m] = __byte_perm(h[m], h[m + 1], 0x5432);

        // tap j, output pair p: taps = j even -> sft[j/2+p], j odd -> h[(j+1)/2+p]
        // acc0 uses weight row s (s<7); acc1 uses weight row s-1 (s>0).
        // Weights read inline (broadcast LDS) to keep register count low.
        #pragma unroll
        for (int j = 0; j < 7; ++j) {
            __half2 w0, w1;
            if (s < 7) w0 = u2h(wsm2[s * 7 + j]);
            if (s > 0) w1 = u2h(wsm2[(s - 1) * 7 + j]);
            #pragma unroll
            for (int p = 0; p < 4; ++p) {
                const __half2 tap = (j & 1) ? u2h(h[((j + 1) >> 1) + p])
                                            : u2h(sft[(j >> 1) + p]);
                if (s < 7) acc0[p] = __hmax2(acc0[p], __hadd2(tap, w0));
                if (s > 0) acc1[p] = __hmax2(acc1[p], __hadd2(tap, w1));
            }
        }
    }

    // ---- convert fp16 -> fp32, store 2x STG.128 per row ----
    {
        float2 f0 = __half22float2(acc0[0]);
        float2 f1 = __half22float2(acc0[1]);
        float2 f2 = __half22float2(acc0[2]);
        float2 f3 = __half22float2(acc0[3]);
        float4* op = reinterpret_cast<float4*>(&go[(R0 + r0) * WW + cbase]);
        op[0] = make_float4(f0.x, f0.y, f1.x, f1.y);
        op[1] = make_float4(f2.x, f2.y, f3.x, f3.y);
    }
    {
        float2 f0 = __half22float2(acc1[0]);
        float2 f1 = __half22float2(acc1[1]);
        float2 f2 = __half22float2(acc1[2]);
        float2 f3 = __half22float2(acc1[3]);
        float4* op = reinterpret_cast<float4*>(&go[(R0 + r0 + 1) * WW + cbase]);
        op[0] = make_float4(f0.x, f0.y, f1.x, f1.y);
        op[1] = make_float4(f2.x, f2.y, f3.x, f3.y);
    }
}

extern "C" void kernel_launch(void* const* d_in, const int* in_sizes, int n_in,
                              void* d_out, int out_size) {
    const float* x  = (const float*)d_in[0];
    const float* wt = (const float*)d_in[1];
    float* out = (float*)d_out;
    morph7x7_h2_kernel<<<BB * CC * 4, NT>>>(x, wt, out);
}